// round 16
// baseline (speedup 1.0000x reference)
#include <cuda_runtime.h>
#include <cuda_bf16.h>
#include <cuda_fp16.h>

// Seq2Seq stacked GRU (L=64, H=64, D=128, B=128, T=256), wavefront-pipelined.
//  K1: precompute layer-0 input projections gi0 = x @ Wih0^T + bih0 (enc+dec)
//  K2: persistent wavefront kernel: 128 CTAs = 64 layers x 2 batch halves,
//      256 threads (8 warps = 4 row-tiles x 2 j-halves).
//      R16: mma.sync.m16n8k16 FP16, single-precision weights AND activations
//      (fp32 accumulate). Half the MMA work of R15's 2-term weight split;
//      error budget spent (predicted ~2e-4 vs 1e-3 gate).
//  K3: output projection out = dec_top @ Wo^T + bo.

#define Hn    64
#define Ln    64
#define Dn    128
#define Bn    128
#define Tn    256
#define G3H   192
#define RINGN 4
#define WSTR  194        // fp32 stride (gi0 / proj kernels)
#define HB    64         // batch rows per CTA

typedef unsigned long long u64;
typedef unsigned int u32;

// Static device scratch (allocation-free rule: __device__ globals only)
__device__ float g_gi0[2][Tn][Bn][G3H];
__device__ u32   g_ring[Ln][2][RINGN][HB][32];   // fp16x2 pairs (k 0..63)
__device__ float g_dectop[Tn][Bn][Hn];
__device__ int   g_prog[Ln * 2];

__device__ __forceinline__ float sigf(float x) {
    return __fdividef(1.0f, 1.0f + __expf(-x));
}
__device__ __forceinline__ float tanhf_fast(float x) {
    return __fdividef(2.0f, 1.0f + __expf(-2.0f * x)) - 1.0f;
}

// ---- packed f32x2 helpers (gi0 / proj kernels) ---------------------------
__device__ __forceinline__ u64 pack2(float x) {
    u64 r; asm("mov.b64 %0, {%1, %1};" : "=l"(r) : "f"(x)); return r;
}
__device__ __forceinline__ void fma2(u64& d, u64 a, u64 b) {
    asm("fma.rn.f32x2 %0, %1, %2, %0;" : "+l"(d) : "l"(a), "l"(b));
}
__device__ __forceinline__ float2 unpack2(u64 v) {
    float2 r; asm("mov.b64 {%0, %1}, %2;" : "=f"(r.x), "=f"(r.y) : "l"(v)); return r;
}
__device__ __forceinline__ u64 ld2(const float* p) { return *(const u64*)p; }

// ---- scoped acquire/release flag ops ------------------------------------
__device__ __forceinline__ int ld_acq(const int* p) {
    int v; asm volatile("ld.acquire.gpu.b32 %0, [%1];" : "=r"(v) : "l"(p) : "memory");
    return v;
}
__device__ __forceinline__ void st_rel(int* p, int v) {
    asm volatile("st.release.gpu.b32 [%0], %1;" :: "l"(p), "r"(v) : "memory");
}
__device__ __forceinline__ void spin_ge(const int* p, int tgt) {
    while (ld_acq(p) < tgt) __nanosleep(64);
}

// ---- tensor-core helpers -------------------------------------------------
__device__ __forceinline__ unsigned smem_u32p(const void* p) {
    unsigned a;
    asm("{ .reg .u64 t; cvta.to.shared.u64 t, %1; cvt.u32.u64 %0, t; }"
        : "=r"(a) : "l"(p));
    return a;
}
__device__ __forceinline__ void ldsm4(u32* r, unsigned addr) {
    asm volatile("ldmatrix.sync.aligned.m8n8.x4.shared.b16 {%0,%1,%2,%3}, [%4];"
                 : "=r"(r[0]), "=r"(r[1]), "=r"(r[2]), "=r"(r[3]) : "r"(addr));
}
__device__ __forceinline__ void mma16816(float* c, const u32* a, u32 b0, u32 b1) {
    asm volatile(
        "mma.sync.aligned.m16n8k16.row.col.f32.f16.f16.f32 "
        "{%0,%1,%2,%3}, {%4,%5,%6,%7}, {%8,%9}, {%0,%1,%2,%3};"
        : "+f"(c[0]), "+f"(c[1]), "+f"(c[2]), "+f"(c[3])
        : "r"(a[0]), "r"(a[1]), "r"(a[2]), "r"(a[3]), "r"(b0), "r"(b1));
}

// (gate, nt-pair) block: B frag for two n-tiles, 2 mma (single precision)
__device__ __forceinline__ void gate_mma1(
    float (*acc2)[4], const u32* a, unsigned whaddr)
{
    u32 bh[4];
    ldsm4(bh, whaddr);
    mma16816(acc2[0], a, bh[0], bh[1]);
    mma16816(acc2[1], a, bh[2], bh[3]);
}

// ---------------------------------------------------------------------------
// Kernel 1: gi0 for layer 0 of both GRUs. grid = (T, 2 halves, 2 models).
// ---------------------------------------------------------------------------
#define GI0_SMEM ((Dn * WSTR + HB * Dn) * 4)

__global__ void __launch_bounds__(256, 1) gi0_kernel(
    const float* __restrict__ ctx,
    const float* __restrict__ encW0, const float* __restrict__ decW0,
    const float* __restrict__ encB,  const float* __restrict__ decB)
{
    extern __shared__ float sm[];
    float* W_s = sm;
    float* x_s = W_s + Dn * WSTR;

    const int t = blockIdx.x, half = blockIdx.y, m = blockIdx.z;
    const float* W0 = m ? decW0 : encW0;
    const float* bi = m ? decB  : encB;
    const int tid = threadIdx.x;
    const int warp = tid >> 5, lane = tid & 31;
    const int bb = warp * 8, jj = lane * 2;

    for (int idx = tid; idx < G3H * Dn; idx += 256) {
        int j = idx >> 7, k = idx & 127;
        W_s[k * WSTR + j] = W0[idx];
    }
    const int tt = m ? (t - 1) : t;
    if (m && t == 0) {
        for (int idx = tid; idx < HB * Dn; idx += 256) x_s[idx] = 0.f;
    } else {
        for (int idx = tid; idx < HB * Dn; idx += 256) {
            int b = idx >> 7, k = idx & 127;
            x_s[idx] = ctx[((size_t)(half * HB + b) * Tn + tt) * Dn + k];
        }
    }
    __syncthreads();

    u64 ar[8], az[8], an[8];
#pragma unroll
    for (int i = 0; i < 8; i++) { ar[i] = 0ull; az[i] = 0ull; an[i] = 0ull; }

    for (int k0 = 0; k0 < Dn; k0 += 4) {
        u64 wr[4], wz[4], wn[4];
#pragma unroll
        for (int kk = 0; kk < 4; kk++) {
            const float* wrow = &W_s[(k0 + kk) * WSTR];
            wr[kk] = ld2(&wrow[jj]);
            wz[kk] = ld2(&wrow[64 + jj]);
            wn[kk] = ld2(&wrow[128 + jj]);
        }
#pragma unroll
        for (int i = 0; i < 8; i++) {
            float4 xv = *(const float4*)&x_s[(bb + i) * Dn + k0];
            u64 xp[4] = {pack2(xv.x), pack2(xv.y), pack2(xv.z), pack2(xv.w)};
#pragma unroll
            for (int kk = 0; kk < 4; kk++) {
                fma2(ar[i], xp[kk], wr[kk]);
                fma2(az[i], xp[kk], wz[kk]);
                fma2(an[i], xp[kk], wn[kk]);
            }
        }
    }
    float2 br = *(const float2*)&bi[jj];
    float2 bz = *(const float2*)&bi[64 + jj];
    float2 bn = *(const float2*)&bi[128 + jj];
#pragma unroll
    for (int i = 0; i < 8; i++) {
        int bg = half * HB + bb + i;
        float* dst = &g_gi0[m][t][bg][0];
        float2 vr = unpack2(ar[i]), vz = unpack2(az[i]), vn = unpack2(an[i]);
        *(float2*)&dst[jj]       = make_float2(vr.x + br.x, vr.y + br.y);
        *(float2*)&dst[64 + jj]  = make_float2(vz.x + bz.x, vz.y + bz.y);
        *(float2*)&dst[128 + jj] = make_float2(vn.x + bn.x, vn.y + bn.y);
    }
}

// ---------------------------------------------------------------------------
// Kernel 2: tensor-core wavefront. 128 CTAs x 256 threads.
// SMEM (bytes), fp16 tiles, 272-byte row stride:
//   WH [256 j'][136] @ 0      (69,632)  j' = gate*64+j; k: 0-63 x, 64-127 h
//   A  [64 row][136] @ 69632  (17,408)  single fp16 [x|h]
//   biases (4 x 64 f32) @ 87040 (1,024)
// ---------------------------------------------------------------------------
#define WH_OFF   0
#define A_OFF    69632
#define BIAS_OFF 87040
#define WAVE_SMEM 88064
#define BSTR 272           // bytes per fp16 tile row

__device__ void stage_w_mma(char* smem,
    const float* __restrict__ Wih, const float* __restrict__ Whh,
    const float* __restrict__ bih, const float* __restrict__ bhh,
    int layer, bool isL0, int tid)
{
    const float* wih_l = isL0 ? Wih : (Wih + (size_t)(layer - 1) * G3H * Hn);
    const float* whh_l = Whh + (size_t)layer * G3H * Hn;
    for (int idx = tid; idx < 256 * 128; idx += 256) {
        int jp = idx >> 7, k = idx & 127;
        int g = jp >> 6, j = jp & 63;
        int sr = (g >= 2 ? 128 : g * 64) + j;
        float w;
        if (k < 64) w = (isL0 || g == 3) ? 0.f : wih_l[sr * 64 + k];
        else        w = (g == 2) ? 0.f : whh_l[sr * 64 + (k - 64)];
        *(__half*)(smem + WH_OFF + jp * BSTR + k * 2) = __float2half_rn(w);
    }
    float* bias = (float*)(smem + BIAS_OFF);
    if (tid < Hn) {
        int hj = tid;
        const float* bi = bih + layer * G3H;
        const float* bh = bhh + layer * G3H;
        bias[hj]        = (isL0 ? 0.f : bi[hj])      + bh[hj];
        bias[64 + hj]   = (isL0 ? 0.f : bi[64 + hj]) + bh[64 + hj];
        bias[128 + hj]  = (isL0 ? 0.f : bi[128 + hj]);
        bias[192 + hj]  = bh[128 + hj];
    }
}

__global__ void __launch_bounds__(256, 1) gru_wave(
    const float* __restrict__ encWih, const float* __restrict__ encWhh,
    const float* __restrict__ encBih, const float* __restrict__ encBhh,
    const float* __restrict__ decWih, const float* __restrict__ decWhh,
    const float* __restrict__ decBih, const float* __restrict__ decBhh)
{
    extern __shared__ char smem[];
    const int tid   = threadIdx.x;
    const int cta   = blockIdx.x;
    const int layer = cta >> 1;
    const int half  = cta & 1;
    const bool isL0 = (layer == 0);
    const int warp = tid >> 5, lane = tid & 31;
    const int rg = warp >> 1;          // row-tile 0..3 (16 rows each)
    const int jh = warp & 1;           // j-half: 32 gate-cols
    const int r0 = rg * 16;
    const int lrow = lane >> 2;        // 0..7
    const int lcol = (lane & 3) * 2;   // 0,2,4,6
    const int g8 = lane >> 3, l7 = lane & 7;

    const unsigned sb  = smem_u32p(smem);
    const unsigned Ab  = sb + A_OFF;
    const unsigned WHb = sb + WH_OFF;
    float* bias = (float*)(smem + BIAS_OFF);

    // per-lane ldmatrix offsets
    const unsigned a_off =
        (unsigned)((r0 + ((g8 & 1) ? 8 : 0) + l7) * BSTR + ((g8 & 2) ? 16 : 0));
    const unsigned b_off =
        (unsigned)((((g8 >= 2) ? 8 : 0) + l7) * BSTR + ((g8 & 1) ? 16 : 0));

    int base = ld_acq(&g_prog[cta]);

    // h0 = 0: zero A h-region (bytes 128..255 per row)
    for (int i = tid; i < HB * 32; i += 256) {
        int row = i >> 5, c = i & 31;
        *(u32*)(smem + A_OFF + row * BSTR + 128 + c * 4) = 0u;
    }
    stage_w_mma(smem, encWih, encWhh, encBih, encBhh, layer, isL0, tid);

    // prologue: stage x(0) for layers > 0
    if (!isL0) {
        spin_ge(&g_prog[cta - 2], base + 1);
        const u32* src = &g_ring[layer - 1][half][0][0][0];
        for (int i = tid; i < HB * 32; i += 256) {
            int row = i >> 5, c = i & 31;
            *(u32*)(smem + A_OFF + row * BSTR + c * 4) = __ldcg(&src[i]);
        }
    }
    __syncthreads();

    // bias regs (reloaded at phase switch)
    float2 crv[4], czv[4], biv[4], bhv[4];
#pragma unroll
    for (int nt = 0; nt < 4; nt++) {
        int j0 = jh * 32 + nt * 8 + lcol;
        crv[nt] = *(const float2*)&bias[j0];
        czv[nt] = *(const float2*)&bias[64 + j0];
        biv[nt] = *(const float2*)&bias[128 + j0];
        bhv[nt] = *(const float2*)&bias[192 + j0];
    }

    float ho[4][4];     // h_old: [nt][q*2+p]
#pragma unroll
    for (int nt = 0; nt < 4; nt++)
#pragma unroll
        for (int c = 0; c < 4; c++) ho[nt][c] = 0.f;

    for (int t = 0; t < 2 * Tn; ++t) {
        if (t == Tn) {   // encoder -> decoder: swap weights, keep h
            __syncthreads();
            stage_w_mma(smem, decWih, decWhh, decBih, decBhh, layer, isL0, tid);
            __syncthreads();
#pragma unroll
            for (int nt = 0; nt < 4; nt++) {
                int j0 = jh * 32 + nt * 8 + lcol;
                crv[nt] = *(const float2*)&bias[j0];
                czv[nt] = *(const float2*)&bias[64 + j0];
                biv[nt] = *(const float2*)&bias[128 + j0];
                bhv[nt] = *(const float2*)&bias[192 + j0];
            }
        }

        // ---- GEMM: acc[gate][nt][4] ----
        float acc[4][4][4];
#pragma unroll
        for (int g = 0; g < 4; g++)
#pragma unroll
            for (int nt = 0; nt < 4; nt++)
#pragma unroll
                for (int c = 0; c < 4; c++) acc[g][nt][c] = 0.f;

        const unsigned jhb = (unsigned)(jh * 32) * BSTR;
        if (!isL0) {
#pragma unroll
            for (int kc = 0; kc < 8; kc++) {
                u32 a[4];
                ldsm4(a, Ab + a_off + kc * 32);
#pragma unroll
                for (int ntp = 0; ntp < 2; ntp++) {
                    unsigned bo = jhb + (unsigned)(ntp * 16) * BSTR + b_off + kc * 32;
                    gate_mma1(&acc[0][ntp * 2], a, WHb + bo);                 // r
                    gate_mma1(&acc[1][ntp * 2], a, WHb + 64u * BSTR + bo);    // z
                    if (kc < 4)
                        gate_mma1(&acc[2][ntp * 2], a, WHb + 128u * BSTR + bo); // inn
                    else
                        gate_mma1(&acc[3][ntp * 2], a, WHb + 192u * BSTR + bo); // hn
                }
            }
        } else {
#pragma unroll
            for (int kc = 4; kc < 8; kc++) {
                u32 a[4];
                ldsm4(a, Ab + a_off + kc * 32);
#pragma unroll
                for (int ntp = 0; ntp < 2; ntp++) {
                    unsigned bo = jhb + (unsigned)(ntp * 16) * BSTR + b_off + kc * 32;
                    gate_mma1(&acc[0][ntp * 2], a, WHb + bo);
                    gate_mma1(&acc[1][ntp * 2], a, WHb + 64u * BSTR + bo);
                    gate_mma1(&acc[3][ntp * 2], a, WHb + 192u * BSTR + bo);
                }
            }
        }

        // ---- epilogue: gates + h update (registers) ----
        const bool wring = (layer < Ln - 1);
        const bool wtop  = (layer == Ln - 1) && (t >= Tn);
        const int m  = (t < Tn) ? 0 : 1;
        const int tt = (t < Tn) ? t : t - Tn;

        u32 hwp[4][2];      // [nt][q] packed fp16x2 of h (j0, j0+1)
        float hnewv[4][4];
#pragma unroll
        for (int nt = 0; nt < 4; nt++) {
            int j0 = jh * 32 + nt * 8 + lcol;
#pragma unroll
            for (int q = 0; q < 2; q++) {
                const float* gp = isL0 ?
                    &g_gi0[m][tt][half * HB + r0 + lrow + q * 8][0] : (const float*)0;
                float2 gr = isL0 ? *(const float2*)&gp[j0]       : make_float2(0.f, 0.f);
                float2 gz = isL0 ? *(const float2*)&gp[64 + j0]  : make_float2(0.f, 0.f);
                float2 gn = isL0 ? *(const float2*)&gp[128 + j0] : make_float2(0.f, 0.f);
                float grv[2] = {gr.x, gr.y}, gzv[2] = {gz.x, gz.y}, gnv[2] = {gn.x, gn.y};
                float hv2[2];
#pragma unroll
                for (int p = 0; p < 2; p++) {
                    int ci = q * 2 + p;
                    float cb[2] = {crv[nt].x, crv[nt].y};
                    float zb[2] = {czv[nt].x, czv[nt].y};
                    float ib[2] = {biv[nt].x, biv[nt].y};
                    float hb2[2] = {bhv[nt].x, bhv[nt].y};
                    float r = sigf(acc[0][nt][ci] + grv[p] + cb[p]);
                    float z = sigf(acc[1][nt][ci] + gzv[p] + zb[p]);
                    float xn = isL0 ? gnv[p] : acc[2][nt][ci];
                    float n = tanhf_fast(xn + ib[p] + r * (acc[3][nt][ci] + hb2[p]));
                    float hnew = (1.0f - z) * n + z * ho[nt][ci];
                    ho[nt][ci] = hnew;
                    hnewv[nt][ci] = hnew;
                    hv2[p] = hnew;
                }
                __half2 hp2 = __floats2half2_rn(hv2[0], hv2[1]);
                hwp[nt][q] = *(u32*)&hp2;
            }
        }

        // ring / dectop writes (global; no SMEM hazard)
        if (wring) {
            if (t >= RINGN)
                spin_ge(&g_prog[cta + 2], base + t - RINGN + 1);
            u32* rdst = &g_ring[layer][half][t & (RINGN - 1)][0][0];
#pragma unroll
            for (int nt = 0; nt < 4; nt++) {
                int ju = (jh * 32 + nt * 8 + lcol) >> 1;
#pragma unroll
                for (int q = 0; q < 2; q++) {
                    int R = r0 + lrow + q * 8;
                    rdst[R * 32 + ju] = hwp[nt][q];
                }
            }
        }
        if (wtop) {
#pragma unroll
            for (int nt = 0; nt < 4; nt++) {
                int j0 = jh * 32 + nt * 8 + lcol;
#pragma unroll
                for (int q = 0; q < 2; q++) {
                    int R = r0 + lrow + q * 8;
                    *(float2*)&g_dectop[t - Tn][half * HB + R][j0] =
                        make_float2(hnewv[nt][q * 2], hnewv[nt][q * 2 + 1]);
                }
            }
        }
        __syncthreads();   // BAR_e: all GEMM reads of A done; ring writes done
        if (tid == 0) st_rel(&g_prog[cta], base + t + 1);   // early release

        // h(t+1) into A h-region
#pragma unroll
        for (int nt = 0; nt < 4; nt++) {
            int j0 = jh * 32 + nt * 8 + lcol;
#pragma unroll
            for (int q = 0; q < 2; q++) {
                int R = r0 + lrow + q * 8;
                *(u32*)(smem + A_OFF + R * BSTR + 128 + j0 * 2) = hwp[nt][q];
            }
        }
        // stage x(t+1) into A x-region (layers > 0)
        if (!isL0 && t + 1 < 2 * Tn) {
            spin_ge(&g_prog[cta - 2], base + t + 2);
            const u32* src = &g_ring[layer - 1][half][(t + 1) & (RINGN - 1)][0][0];
            for (int i = tid; i < HB * 32; i += 256) {
                int row = i >> 5, c = i & 31;
                *(u32*)(smem + A_OFF + row * BSTR + c * 4) = __ldcg(&src[i]);
            }
        }
        __syncthreads();   // BAR_d: A ready for next GEMM
    }
}

// ---------------------------------------------------------------------------
// Kernel 3: output projection  out = dec_top @ Wo^T + bo. grid = (T, 2).
// ---------------------------------------------------------------------------
#define PSTR 130
#define PROJ_SMEM ((Hn * PSTR + HB * Hn) * 4)

__global__ void __launch_bounds__(256, 1) proj_kernel(
    const float* __restrict__ Wo, const float* __restrict__ bo,
    float* __restrict__ out)
{
    extern __shared__ float sm[];
    float* W_s = sm;
    float* x_s = W_s + Hn * PSTR;

    const int t = blockIdx.x, half = blockIdx.y;
    const int tid = threadIdx.x;
    const int warp = tid >> 5, lane = tid & 31;
    const int bb = warp * 8, jj = lane * 2;

    for (int idx = tid; idx < Dn * Hn; idx += 256) {
        int d = idx >> 6, k = idx & 63;
        W_s[k * PSTR + d] = Wo[idx];
    }
    for (int idx = tid; idx < HB * Hn; idx += 256) {
        x_s[idx] = g_dectop[t][half * HB + (idx >> 6)][idx & 63];
    }
    __syncthreads();

    u64 a0[8], a1[8];
#pragma unroll
    for (int i = 0; i < 8; i++) { a0[i] = 0ull; a1[i] = 0ull; }

    for (int k0 = 0; k0 < Hn; k0 += 4) {
        u64 w0[4], w1[4];
#pragma unroll
        for (int kk = 0; kk < 4; kk++) {
            const float* wrow = &W_s[(k0 + kk) * PSTR];
            w0[kk] = ld2(&wrow[jj]);
            w1[kk] = ld2(&wrow[64 + jj]);
        }
#pragma unroll
        for (int i = 0; i < 8; i++) {
            float4 xv = *(const float4*)&x_s[(bb + i) * Hn + k0];
            u64 xp[4] = {pack2(xv.x), pack2(xv.y), pack2(xv.z), pack2(xv.w)};
#pragma unroll
            for (int kk = 0; kk < 4; kk++) {
                fma2(a0[i], xp[kk], w0[kk]);
                fma2(a1[i], xp[kk], w1[kk]);
            }
        }
    }
    float2 b0 = *(const float2*)&bo[jj];
    float2 b1 = *(const float2*)&bo[64 + jj];
#pragma unroll
    for (int i = 0; i < 8; i++) {
        int bg = half * HB + bb + i;
        float* o = &out[((size_t)bg * Tn + t) * Dn];
        float2 v0 = unpack2(a0[i]), v1 = unpack2(a1[i]);
        *(float2*)&o[jj]      = make_float2(v0.x + b0.x, v0.y + b0.y);
        *(float2*)&o[64 + jj] = make_float2(v1.x + b1.x, v1.y + b1.y);
    }
}

// ---------------------------------------------------------------------------
extern "C" void kernel_launch(void* const* d_in, const int* in_sizes, int n_in,
                              void* d_out, int out_size) {
    const float* ctx     = (const float*)d_in[0];
    const float* encW0   = (const float*)d_in[1];
    const float* encWih  = (const float*)d_in[2];
    const float* encWhh  = (const float*)d_in[3];
    const float* encBih  = (const float*)d_in[4];
    const float* encBhh  = (const float*)d_in[5];
    const float* decW0   = (const float*)d_in[6];
    const float* decWih  = (const float*)d_in[7];
    const float* decWhh  = (const float*)d_in[8];
    const float* decBih  = (const float*)d_in[9];
    const float* decBhh  = (const float*)d_in[10];
    const float* Wo      = (const float*)d_in[11];
    const float* bo      = (const float*)d_in[12];
    float* out = (float*)d_out;

    cudaFuncSetAttribute(gi0_kernel,
        cudaFuncAttributeMaxDynamicSharedMemorySize, GI0_SMEM);
    cudaFuncSetAttribute(gru_wave,
        cudaFuncAttributeMaxDynamicSharedMemorySize, WAVE_SMEM);
    cudaFuncSetAttribute(proj_kernel,
        cudaFuncAttributeMaxDynamicSharedMemorySize, PROJ_SMEM);

    gi0_kernel<<<dim3(Tn, 2, 2), 256, GI0_SMEM>>>(ctx, encW0, decW0,
                                                  encBih, decBih);
    gru_wave<<<Ln * 2, 256, WAVE_SMEM>>>(encWih, encWhh, encBih, encBhh,
                                         decWih, decWhh, decBih, decBhh);
    proj_kernel<<<dim3(Tn, 2), 256, PROJ_SMEM>>>(Wo, bo, out);
}